// round 4
// baseline (speedup 1.0000x reference)
#include <cuda_runtime.h>
#include <cuda_bf16.h>
#include <math.h>
#include <float.h>

#define NN 100000
#define EE 1600000
#define FIN 50
#define FP 64          // padded x stride
#define CC 32
#define SCAN_B 1024

// ---------------- scratch (__device__ globals; no allocation) ----------------
__device__ int g_cnt[NN];
__device__ int g_scan[NN];
__device__ int g_bsum[128];
__device__ int g_boff[128];
__device__ int g_rowptr[NN + 1];
__device__ int g_cursor[NN];
__device__ int g_adj[EE];
__device__ float g_xpad[NN * FP];   // x padded to 64-stride, zeros beyond 50
__device__ float g_ha[NN * CC];
__device__ float g_hb[NN * CC];

// ---------------- x padding ----------------
__global__ void __launch_bounds__(256) pad_x(const float* __restrict__ x) {
    int i = blockIdx.x * blockDim.x + threadIdx.x;
    if (i >= NN * FP) return;
    int n = i >> 6;
    int c = i & 63;
    g_xpad[i] = (c < FIN) ? x[n * FIN + c] : 0.0f;
}

// ---------------- CSR build ----------------
__global__ void __launch_bounds__(256) zero_cnt() {
    int i = blockIdx.x * blockDim.x + threadIdx.x;
    if (i < NN) g_cnt[i] = 0;
}

__global__ void __launch_bounds__(256) hist_dst(const int* __restrict__ ei, int E) {
    int e = blockIdx.x * blockDim.x + threadIdx.x;
    if (e < E) atomicAdd(&g_cnt[ei[E + e]], 1);
}

__global__ void __launch_bounds__(SCAN_B) scan_blocks() {
    __shared__ int s[SCAN_B];
    int i = blockIdx.x * SCAN_B + threadIdx.x;
    int v = (i < NN) ? g_cnt[i] : 0;
    s[threadIdx.x] = v;
    __syncthreads();
#pragma unroll
    for (int off = 1; off < SCAN_B; off <<= 1) {
        int t = (threadIdx.x >= off) ? s[threadIdx.x - off] : 0;
        __syncthreads();
        s[threadIdx.x] += t;
        __syncthreads();
    }
    if (i < NN) g_scan[i] = s[threadIdx.x];
    if (threadIdx.x == SCAN_B - 1) g_bsum[blockIdx.x] = s[SCAN_B - 1];
}

__global__ void __launch_bounds__(128) scan_bsums(int nb) {
    __shared__ int s[128];
    int t = threadIdx.x;
    int v = (t < nb) ? g_bsum[t] : 0;
    s[t] = v;
    __syncthreads();
#pragma unroll
    for (int off = 1; off < 128; off <<= 1) {
        int u = (t >= off) ? s[t - off] : 0;
        __syncthreads();
        s[t] += u;
        __syncthreads();
    }
    if (t < nb) g_boff[t] = s[t] - v;
}

__global__ void __launch_bounds__(256) make_rowptr(int E) {
    int i = blockIdx.x * blockDim.x + threadIdx.x;
    if (i < NN) {
        int excl = g_scan[i] - g_cnt[i] + g_boff[i / SCAN_B];
        g_rowptr[i] = excl;
        g_cursor[i] = excl;
    }
    if (i == 0) g_rowptr[NN] = E;
}

__global__ void __launch_bounds__(256) csr_scatter(const int* __restrict__ ei, int E) {
    int e = blockIdx.x * blockDim.x + threadIdx.x;
    if (e >= E) return;
    int s = ei[e];
    int d = ei[E + e];
    int pos = atomicAdd(&g_cursor[d], 1);
    g_adj[pos] = s;
}

// ---------------- layer 1: gather-max over padded x + GEMV + relu ----------------
__global__ void __launch_bounds__(256) layer1(const float* __restrict__ Wl,
                                              const float* __restrict__ bl,
                                              const float* __restrict__ Wr) {
    __shared__ float sWl[FIN * CC];
    __shared__ float sWr[FIN * CC];
    __shared__ float sbl[CC];
    for (int i = threadIdx.x; i < FIN * CC; i += blockDim.x) {
        sWl[i] = Wl[i];
        sWr[i] = Wr[i];
    }
    if (threadIdx.x < CC) sbl[threadIdx.x] = bl[threadIdx.x];
    __syncthreads();

    int node = (blockIdx.x * blockDim.x + threadIdx.x) >> 5;
    int lane = threadIdx.x & 31;
    if (node >= NN) return;

    int beg = g_rowptr[node];
    int end = g_rowptr[node + 1];
    int c1 = 32 + lane;

    float m0a = -FLT_MAX, m0b = -FLT_MAX;
    float m1a = -FLT_MAX, m1b = -FLT_MAX;
    int p = beg;
    for (; p + 4 <= end; p += 4) {
        const float* r0 = g_xpad + ((long)g_adj[p]     << 6);
        const float* r1 = g_xpad + ((long)g_adj[p + 1] << 6);
        const float* r2 = g_xpad + ((long)g_adj[p + 2] << 6);
        const float* r3 = g_xpad + ((long)g_adj[p + 3] << 6);
        float a0 = r0[lane], a1 = r1[lane], a2 = r2[lane], a3 = r3[lane];
        float b0 = r0[c1],   b1 = r1[c1],   b2 = r2[c1],   b3 = r3[c1];
        m0a = fmaxf(m0a, fmaxf(a0, a1));
        m0b = fmaxf(m0b, fmaxf(a2, a3));
        m1a = fmaxf(m1a, fmaxf(b0, b1));
        m1b = fmaxf(m1b, fmaxf(b2, b3));
    }
    for (; p < end; ++p) {
        const float* r0 = g_xpad + ((long)g_adj[p] << 6);
        m0a = fmaxf(m0a, r0[lane]);
        m1a = fmaxf(m1a, r0[c1]);
    }
    float m0 = fmaxf(m0a, m0b);
    float m1 = fmaxf(m1a, m1b);
    if (beg == end) { m0 = 0.0f; m1 = 0.0f; }

    const float* xn = g_xpad + ((long)node << 6);
    float x0 = xn[lane];
    float x1 = xn[c1];

    float acc = sbl[lane];
#pragma unroll
    for (int k = 0; k < FIN; k++) {
        float a, xv;
        if (k < 32) {
            a = __shfl_sync(0xffffffff, m0, k);
            xv = __shfl_sync(0xffffffff, x0, k);
        } else {
            a = __shfl_sync(0xffffffff, m1, k - 32);
            xv = __shfl_sync(0xffffffff, x1, k - 32);
        }
        acc += a * sWl[k * CC + lane] + xv * sWr[k * CC + lane];
    }
    g_ha[node * CC + lane] = fmaxf(acc, 0.0f);
}

// ---------------- layers 2/3: gather-max(d=32) + GEMV (+relu | +log_softmax) --
template <bool FINAL>
__global__ void __launch_bounds__(256) layer23(const float* __restrict__ hin,
                                               float* __restrict__ hout,
                                               const float* __restrict__ Wl,
                                               const float* __restrict__ bl,
                                               const float* __restrict__ Wr) {
    __shared__ float sWl[CC * CC];
    __shared__ float sWr[CC * CC];
    __shared__ float sbl[CC];
    for (int i = threadIdx.x; i < CC * CC; i += blockDim.x) {
        sWl[i] = Wl[i];
        sWr[i] = Wr[i];
    }
    if (threadIdx.x < CC) sbl[threadIdx.x] = bl[threadIdx.x];
    __syncthreads();

    int node = (blockIdx.x * blockDim.x + threadIdx.x) >> 5;
    int lane = threadIdx.x & 31;
    if (node >= NN) return;

    int beg = g_rowptr[node];
    int end = g_rowptr[node + 1];

    float ma = -FLT_MAX, mb = -FLT_MAX;
    int p = beg;
    for (; p + 4 <= end; p += 4) {
        float v0 = hin[g_adj[p]     * CC + lane];
        float v1 = hin[g_adj[p + 1] * CC + lane];
        float v2 = hin[g_adj[p + 2] * CC + lane];
        float v3 = hin[g_adj[p + 3] * CC + lane];
        ma = fmaxf(ma, fmaxf(v0, v1));
        mb = fmaxf(mb, fmaxf(v2, v3));
    }
    for (; p < end; ++p) {
        ma = fmaxf(ma, hin[g_adj[p] * CC + lane]);
    }
    float m = fmaxf(ma, mb);
    if (beg == end) m = 0.0f;

    float x_l = hin[node * CC + lane];

    float acc = sbl[lane];
#pragma unroll
    for (int k = 0; k < CC; k++) {
        float a = __shfl_sync(0xffffffff, m, k);
        float xv = __shfl_sync(0xffffffff, x_l, k);
        acc += a * sWl[k * CC + lane] + xv * sWr[k * CC + lane];
    }

    if (!FINAL) {
        hout[node * CC + lane] = fmaxf(acc, 0.0f);
    } else {
        float mx = acc;
#pragma unroll
        for (int o = 16; o > 0; o >>= 1) mx = fmaxf(mx, __shfl_xor_sync(0xffffffff, mx, o));
        float e = expf(acc - mx);
        float s = e;
#pragma unroll
        for (int o = 16; o > 0; o >>= 1) s += __shfl_xor_sync(0xffffffff, s, o);
        hout[node * CC + lane] = acc - mx - logf(s);
    }
}

extern "C" void kernel_launch(void* const* d_in, const int* in_sizes, int n_in,
                              void* d_out, int out_size) {
    const float* x = (const float*)d_in[0];
    const int* ei = (const int*)d_in[1];
    const float* Wl1 = (const float*)d_in[2];
    const float* bl1 = (const float*)d_in[3];
    const float* Wr1 = (const float*)d_in[4];
    const float* Wl2 = (const float*)d_in[5];
    const float* bl2 = (const float*)d_in[6];
    const float* Wr2 = (const float*)d_in[7];
    const float* Wl3 = (const float*)d_in[8];
    const float* bl3 = (const float*)d_in[9];
    const float* Wr3 = (const float*)d_in[10];
    float* out = (float*)d_out;

    int E = in_sizes[1] / 2;

    const int TB = 256;
    int nblk = (NN + TB - 1) / TB;
    int eblk = (E + TB - 1) / TB;
    int sblk = (NN + SCAN_B - 1) / SCAN_B;
    int node_blocks = (NN * 32 + TB - 1) / TB;
    int padblk = (NN * FP + TB - 1) / TB;

    // ---- x padding + CSR build ----
    pad_x<<<padblk, TB>>>(x);
    zero_cnt<<<nblk, TB>>>();
    hist_dst<<<eblk, TB>>>(ei, E);
    scan_blocks<<<sblk, SCAN_B>>>();
    scan_bsums<<<1, 128>>>(sblk);
    make_rowptr<<<nblk, TB>>>(E);
    csr_scatter<<<eblk, TB>>>(ei, E);

    // ---- fused layers ----
    float* ha;  cudaGetSymbolAddress((void**)&ha, g_ha);
    float* hb;  cudaGetSymbolAddress((void**)&hb, g_hb);
    layer1<<<node_blocks, TB>>>(Wl1, bl1, Wr1);
    layer23<false><<<node_blocks, TB>>>(ha, hb, Wl2, bl2, Wr2);
    layer23<true><<<node_blocks, TB>>>(hb, out, Wl3, bl3, Wr3);
}